// round 14
// baseline (speedup 1.0000x reference)
#include <cuda_runtime.h>

// Output: [N+2E, 2E+N] = [5120, 5120] float32, row-major.
//   rows [0, N):        [ M (N x E) | 0 | 0 ]
//   rows [N, N+E):      [ 0 | I_E | -M^T (E x N) ]
//   rows [N+E, N+2E):   [ diag(z) | diag(y) | 0 ]
//
// Champion structure (R13: one row / tile per 256-thread block, STG.128 with
// evict-first .cs policy). Region order puts the load-latency-bound transpose
// tiles FIRST so their cold M reads overlap the store-bound regions:
//   [0, 2048):     TR : -M^T 32x32 smem tile transpose
//   [2048, 4096):  BOT: row N+E+e: zeros + z/y diagonal
//   [4096, 6144):  MID: row N+e, cols [0,4096): zeros + identity
//   [6144, 7168):  TOP: row b. M copy cols [0,2048) + zeros [2048,5120)

#define NN   1024
#define EE   2048
#define SIGW 64
#define CC   (2 * EE + NN)   // 5120
#define C4   (CC / 4)        // 1280
#define DTC  1e-6f

#define TR_B  2048
#define BOT_B 2048
#define MID_B 2048
#define TOP_B 1024
#define GRID_B (TR_B + BOT_B + MID_B + TOP_B)   // 7168

__global__ void __launch_bounds__(256)
coeff_build_kernel(const float* __restrict__ M,
                   const float* __restrict__ params,
                   const float* __restrict__ sw_params,
                   const int*   __restrict__ kinds,
                   const int*   __restrict__ time_ptr,
                   float*       __restrict__ out)
{
    __shared__ float tile[32][33];

    const int b   = blockIdx.x;
    const int tid = threadIdx.x;
    const float4 zero4 = make_float4(0.f, 0.f, 0.f, 0.f);
    float4* out4 = reinterpret_cast<float4*>(out);

    if (b < TR_B) {
        // ---- TR: -M^T via smem transpose: out[N+e][2E+n] = -M[n][e]. ----
        const int t  = b;
        const int tn = t & 31;              // 32 tiles along n
        const int te = t >> 5;              // 64 tiles along e
        const int n0 = tn * 32;
        const int e0 = te * 32;
        const int tx = tid & 31;
        const int ty = tid >> 5;            // 0..7

        #pragma unroll
        for (int i = 0; i < 4; i++) {
            const int r = ty + i * 8;       // local n
            tile[r][tx] = M[(size_t)(n0 + r) * EE + (e0 + tx)];
        }
        __syncthreads();

        const int r = tid >> 3;             // local e, 0..31
        const int q = tid & 7;              // float4 slot along n, 0..7
        float4 v;
        v.x = -tile[q * 4 + 0][r];
        v.y = -tile[q * 4 + 1][r];
        v.z = -tile[q * 4 + 2][r];
        v.w = -tile[q * 4 + 3][r];
        __stcs(reinterpret_cast<float4*>(
            out + (size_t)(NN + e0 + r) * CC + (2 * EE + n0 + q * 4)), v);
        return;
    }

    if (b < TR_B + BOT_B) {
        // ---- BOT: row N+E+e. diag(z) at col e, diag(y) at col E+e, rest 0. ----
        const int e = b - TR_B;
        float4* orow = out4 + (size_t)(NN + EE + e) * C4;

        const int   tm    = *time_ptr;
        const float p     = __ldg(params + e);
        const int   kk    = __ldg(kinds + e);
        const bool  sw_on = __ldg(sw_params + (size_t)e * SIGW + tm) > 0.0f; // sigmoid(x)>0.5 <=> x>0
        const float ndt   = -DTC / p;
        float z, y;
        switch (kk) {
            case 0:  z = -p;                  y = 1.0f;                 break; // R
            case 1:  z = 0.0f;                y = 1.0f;                 break; // IVS
            case 2:  z = 1.0f;                y = 0.0f;                 break; // VC
            case 3:  z = sw_on ? 0.0f : 1.0f; y = sw_on ? 1.0f : 0.0f;  break; // SW
            case 4:  z = ndt;                 y = 1.0f;                 break; // C
            default: z = 1.0f;                y = ndt;                  break; // L
        }

        const int zf4  = e >> 2;            // float4 slot of z
        const int yf4  = 512 + (e >> 2);    // float4 slot of y
        const int comp = e & 3;

        #pragma unroll
        for (int k = 0; k < 5; k++) {
            const int c4 = tid + k * 256;
            float4 v = zero4;
            if (c4 == zf4) ((float*)&v)[comp] = z;
            if (c4 == yf4) ((float*)&v)[comp] = y;
            __stcs(orow + c4, v);
        }
        return;
    }

    if (b < TR_B + BOT_B + MID_B) {
        // ---- MID: row N+e, cols [0,4096): zeros + 1.0 at col (E + e). ----
        const int e = b - (TR_B + BOT_B);
        float4* orow = out4 + (size_t)(NN + e) * C4;
        const int idf4  = 512 + (e >> 2);   // float4 slot of the identity 1.0
        const int idcmp = e & 3;
        #pragma unroll
        for (int k = 0; k < 4; k++) {
            const int c4 = tid + k * 256;
            float4 v = zero4;
            if (c4 == idf4) ((float*)&v)[idcmp] = 1.0f;
            __stcs(orow + c4, v);
        }
        return;
    }

    // ---- TOP: row. Unconditional copy (512 f4) + zeros (768 f4). ----
    {
        const int row = b - (TR_B + BOT_B + MID_B);
        const float4* Mrow = reinterpret_cast<const float4*>(M + (size_t)row * EE);
        float4* orow = out4 + (size_t)row * C4;
        __stcs(orow + tid,        __ldg(Mrow + tid));
        __stcs(orow + tid + 256,  __ldg(Mrow + tid + 256));
        __stcs(orow + 512 + tid,  zero4);
        __stcs(orow + 768 + tid,  zero4);
        __stcs(orow + 1024 + tid, zero4);
    }
}

extern "C" void kernel_launch(void* const* d_in, const int* in_sizes, int n_in,
                              void* d_out, int out_size)
{
    const float* M         = (const float*)d_in[0];
    const float* params    = (const float*)d_in[1];
    const float* sw_params = (const float*)d_in[2];
    const int*   kinds     = (const int*)d_in[3];
    const int*   time_ptr  = (const int*)d_in[4];

    coeff_build_kernel<<<GRID_B, 256>>>(M, params, sw_params, kinds, time_ptr,
                                        (float*)d_out);
}

// round 15
// speedup vs baseline: 1.1218x; 1.1218x over previous
#include <cuda_runtime.h>

// FINAL (R13 champion, reproduced verbatim).
// Output: [N+2E, 2E+N] = [5120, 5120] float32, row-major.
//   rows [0, N):        [ M (N x E) | 0 | 0 ]
//   rows [N, N+E):      [ 0 | I_E | -M^T (E x N) ]
//   rows [N+E, N+2E):   [ diag(z) | diag(y) | 0 ]
//
// One launch; one output row (or 32x32 transpose tile) per 256-thread block;
// STG.128 with evict-first (.cs) policy on all output writes.
//   [0, 1024):     TOP: row b. M copy cols [0,2048) + zeros [2048,5120)
//   [1024, 3072):  MID: row N+e, cols [0,4096): zeros + identity
//   [3072, 5120):  TR : -M^T 32x32 smem tile transpose
//   [5120, 7168):  BOT: row N+E+e: zeros + z/y diagonal

#define NN   1024
#define EE   2048
#define SIGW 64
#define CC   (2 * EE + NN)   // 5120
#define C4   (CC / 4)        // 1280
#define DTC  1e-6f

#define TOP_B 1024
#define MID_B 2048
#define TR_B  2048
#define BOT_B 2048
#define GRID_B (TOP_B + MID_B + TR_B + BOT_B)   // 7168

__global__ void __launch_bounds__(256)
coeff_build_kernel(const float* __restrict__ M,
                   const float* __restrict__ params,
                   const float* __restrict__ sw_params,
                   const int*   __restrict__ kinds,
                   const int*   __restrict__ time_ptr,
                   float*       __restrict__ out)
{
    __shared__ float tile[32][33];

    const int b   = blockIdx.x;
    const int tid = threadIdx.x;
    const float4 zero4 = make_float4(0.f, 0.f, 0.f, 0.f);
    float4* out4 = reinterpret_cast<float4*>(out);

    if (b < TOP_B) {
        // ---- TOP: row = b. Unconditional copy (512 f4) + zeros (768 f4). ----
        const int row = b;
        const float4* Mrow = reinterpret_cast<const float4*>(M + (size_t)row * EE);
        float4* orow = out4 + (size_t)row * C4;
        __stcs(orow + tid,        __ldg(Mrow + tid));
        __stcs(orow + tid + 256,  __ldg(Mrow + tid + 256));
        __stcs(orow + 512 + tid,  zero4);
        __stcs(orow + 768 + tid,  zero4);
        __stcs(orow + 1024 + tid, zero4);
        return;
    }

    if (b < TOP_B + MID_B) {
        // ---- MID: row N+e, cols [0,4096): zeros + 1.0 at col (E + e). ----
        const int e = b - TOP_B;
        float4* orow = out4 + (size_t)(NN + e) * C4;
        const int idf4  = 512 + (e >> 2);   // float4 slot of the identity 1.0
        const int idcmp = e & 3;
        #pragma unroll
        for (int k = 0; k < 4; k++) {
            const int c4 = tid + k * 256;
            float4 v = zero4;
            if (c4 == idf4) ((float*)&v)[idcmp] = 1.0f;
            __stcs(orow + c4, v);
        }
        return;
    }

    if (b < TOP_B + MID_B + TR_B) {
        // ---- TR: -M^T via smem transpose: out[N+e][2E+n] = -M[n][e]. ----
        const int t  = b - (TOP_B + MID_B);
        const int tn = t & 31;              // 32 tiles along n
        const int te = t >> 5;              // 64 tiles along e
        const int n0 = tn * 32;
        const int e0 = te * 32;
        const int tx = tid & 31;
        const int ty = tid >> 5;            // 0..7

        #pragma unroll
        for (int i = 0; i < 4; i++) {
            const int r = ty + i * 8;       // local n
            tile[r][tx] = M[(size_t)(n0 + r) * EE + (e0 + tx)];
        }
        __syncthreads();

        const int r = tid >> 3;             // local e, 0..31
        const int q = tid & 7;              // float4 slot along n, 0..7
        float4 v;
        v.x = -tile[q * 4 + 0][r];
        v.y = -tile[q * 4 + 1][r];
        v.z = -tile[q * 4 + 2][r];
        v.w = -tile[q * 4 + 3][r];
        __stcs(reinterpret_cast<float4*>(
            out + (size_t)(NN + e0 + r) * CC + (2 * EE + n0 + q * 4)), v);
        return;
    }

    // ---- BOT: row N+E+e. diag(z) at col e, diag(y) at col E+e, rest 0. ----
    {
        const int e = b - (TOP_B + MID_B + TR_B);
        float4* orow = out4 + (size_t)(NN + EE + e) * C4;

        const int   tm    = *time_ptr;
        const float p     = __ldg(params + e);
        const int   kk    = __ldg(kinds + e);
        const bool  sw_on = __ldg(sw_params + (size_t)e * SIGW + tm) > 0.0f; // sigmoid(x)>0.5 <=> x>0
        const float ndt   = -DTC / p;
        float z, y;
        switch (kk) {
            case 0:  z = -p;                  y = 1.0f;                 break; // R
            case 1:  z = 0.0f;                y = 1.0f;                 break; // IVS
            case 2:  z = 1.0f;                y = 0.0f;                 break; // VC
            case 3:  z = sw_on ? 0.0f : 1.0f; y = sw_on ? 1.0f : 0.0f;  break; // SW
            case 4:  z = ndt;                 y = 1.0f;                 break; // C
            default: z = 1.0f;                y = ndt;                  break; // L
        }

        const int zf4  = e >> 2;            // float4 slot of z
        const int yf4  = 512 + (e >> 2);    // float4 slot of y
        const int comp = e & 3;

        #pragma unroll
        for (int k = 0; k < 5; k++) {
            const int c4 = tid + k * 256;
            float4 v = zero4;
            if (c4 == zf4) ((float*)&v)[comp] = z;
            if (c4 == yf4) ((float*)&v)[comp] = y;
            __stcs(orow + c4, v);
        }
    }
}

extern "C" void kernel_launch(void* const* d_in, const int* in_sizes, int n_in,
                              void* d_out, int out_size)
{
    const float* M         = (const float*)d_in[0];
    const float* params    = (const float*)d_in[1];
    const float* sw_params = (const float*)d_in[2];
    const int*   kinds     = (const int*)d_in[3];
    const int*   time_ptr  = (const int*)d_in[4];

    coeff_build_kernel<<<GRID_B, 256>>>(M, params, sw_params, kinds, time_ptr,
                                        (float*)d_out);
}